// round 14
// baseline (speedup 1.0000x reference)
#include <cuda_runtime.h>
#include <math.h>

#define BB   8
#define NN   40000
#define DD   256
#define SS   128
#define HID  64
#define RPB  4          // rows per block in fused middle kernel
#define NACC 72         // accumulation blocks per batch
#define PTS  556        // points per accum block (72*556 = 40032 >= 40000)

// ---------------- device scratch (no allocations allowed) ----------------
__device__ long long g_p1[BB * NACC * SS];   // packed (cnt, z) partials
__device__ long long g_p2[BB * NACC * SS];   // packed (x, y) partials
__device__ float     g_a4[BB * SS * DD];     // final per-superpoint table (masked)

__device__ __forceinline__ float geluf(float x) { return x * normcdff(x); }

// ---------------- K1: segment accumulation, 2 packed smem atomics per point ----------------
// Fixed point scale 2^17. A1 = cnt*2^32 + (z17 + 2^31); A2 = x17*2^32 + (y17 + 2^31).
// 2-way replicated histograms (warp parity) to halve smem-atomic conflicts.
__global__ __launch_bounds__(256) void accum_kernel(const float* __restrict__ coords,
                                                    const int* __restrict__ labels) {
    __shared__ unsigned long long s1[2][SS], s2[2][SS];
    int b = blockIdx.y;
    int j = blockIdx.x;
    int base = j * PTS;
    int tid = threadIdx.x;
    int rep = (tid >> 5) & 1;

    for (int i = tid; i < 2 * SS; i += 256) {
        ((unsigned long long*)s1)[i] = 0ULL;
        ((unsigned long long*)s2)[i] = 0ULL;
    }
    __syncthreads();

    const float SC = 131072.0f; // 2^17
    #pragma unroll 3
    for (int i = tid; i < PTS; i += 256) {
        int n = base + i;
        if (n < NN) {
            long long pt = (long long)b * NN + n;
            int lab = __ldg(labels + pt) & (SS - 1);
            const float* c = coords + pt * 3;
            float fx = __ldg(c + 0), fy = __ldg(c + 1), fz = __ldg(c + 2);
            long long x17 = __float2int_rn(fx * SC);
            long long y17 = __float2int_rn(fy * SC);
            long long z17 = __float2int_rn(fz * SC);
            unsigned long long a1 = (unsigned long long)((1LL << 32) + (1LL << 31) + z17);
            unsigned long long a2 = (unsigned long long)((x17 << 32) + (1LL << 31) + y17);
            atomicAdd(&s1[rep][lab], a1);
            atomicAdd(&s2[rep][lab], a2);
        }
    }
    __syncthreads();

    if (tid < SS) {
        g_p1[(b * NACC + j) * SS + tid] = (long long)(s1[0][tid] + s1[1][tid]);
        g_p2[(b * NACC + j) * SS + tid] = (long long)(s2[0][tid] + s2[1][tid]);
    }
}

// ---------------- K2: fully fused middle (centers -> rel -> MLP -> LN -> a4) ----------------
__global__ __launch_bounds__(256) void middle_kernel(
    const float* __restrict__ W1, const float* __restrict__ b1,
    const float* __restrict__ W2, const float* __restrict__ b2,
    const float* __restrict__ W3, const float* __restrict__ b3,
    const float* __restrict__ lng, const float* __restrict__ lnb,
    const float* __restrict__ W4, const float* __restrict__ b4)
{
    int b   = blockIdx.y;
    int r0  = blockIdx.x * RPB;
    int tid = threadIdx.x;
    int lane = tid & 31, w = tid >> 5;

    __shared__ float cx[SS], cy[SS], cz[SS], vm[SS];
    __shared__ float relS[RPB][4];
    __shared__ float maskS[RPB];
    __shared__ __align__(16) float h1s[RPB][HID];
    __shared__ __align__(16) float h2s[RPB][DD];
    __shared__ __align__(16) float ys [RPB][DD];
    __shared__ float red[8 * RPB];
    __shared__ float s_nv;

    // ---- reduce packed partials -> centers for ALL superpoints of this batch ----
    if (tid < SS) {
        long long v1 = 0, v2 = 0;
        #pragma unroll 8
        for (int j = 0; j < NACC; j++) {
            v1 += g_p1[(b * NACC + j) * SS + tid];
            v2 += g_p2[(b * NACC + j) * SS + tid];
        }
        const long long T31 = 3LL << 31;
        long long cnt = (v1 + (T31 >> 1)) / T31;        // V1 = cnt*3*2^31 + z_sum
        long long zs  = v1 - cnt * T31;
        long long u   = v2 - (cnt << 31);               // = x_sum*2^32 + y_sum
        int  ylow = (int)(unsigned int)(u & 0xFFFFFFFFULL);
        long long xs = (u - (long long)ylow) >> 32;

        float cf = (float)cnt;
        float dc = fmaxf(cf, 1.0f);
        const float INV = 1.0f / 131072.0f;
        cx[tid] = ((float)xs   * INV) / dc;
        cy[tid] = ((float)ylow * INV) / dc;
        cz[tid] = ((float)zs   * INV) / dc;
        vm[tid] = (cf >= 2.0f) ? 1.0f : 0.0f;
    }
    __syncthreads();
    if (tid == 0) {
        float t = 0.f;
        #pragma unroll 8
        for (int i = 0; i < SS; i++) t += vm[i];
        s_nv = t;
    }
    __syncthreads();
    float nv    = s_nv;
    float denom = fmaxf(nv, 1.0f);

    // ---- rel features: warp r (0..3) handles row r0+r ----
    if (w < RPB) {
        int s = r0 + w;
        float xs = cx[s], ysv = cy[s], zs = cz[s];
        float msum = 0.f, mind = INFINITY, fcnt = 0.f;
        #pragma unroll
        for (int t = lane; t < SS; t += 32) {
            float dx = xs - cx[t], dy = ysv - cy[t], dz = zs - cz[t];
            float d2 = dx * dx + dy * dy + dz * dz;
            float dist = (d2 > 0.f) ? sqrtf(d2) : 0.f;
            float v = vm[t];
            msum += dist * v;
            if (v > 0.f) mind = fminf(mind, dist);
            fcnt += (zs > cz[t] ? 1.0f : 0.0f) * v;
        }
        #pragma unroll
        for (int o = 16; o > 0; o >>= 1) {
            msum += __shfl_xor_sync(0xffffffffu, msum, o);
            mind  = fminf(mind, __shfl_xor_sync(0xffffffffu, mind, o));
            fcnt += __shfl_xor_sync(0xffffffffu, fcnt, o);
        }
        if (lane == 0) {
            relS[w][0] = msum / denom;
            relS[w][1] = mind;
            relS[w][2] = zs;
            relS[w][3] = fcnt / denom;
            maskS[w]   = vm[s] * ((nv >= 2.0f) ? 1.0f : 0.0f);
        }
    }
    __syncthreads();

    // ---- h1 = gelu(rel @ W1 + b1): tid -> (r = tid>>6, j = tid&63) ----
    {
        int r = tid >> 6, j = tid & 63;
        float a = b1[j]
                + relS[r][0] * W1[0 * HID + j]
                + relS[r][1] * W1[1 * HID + j]
                + relS[r][2] * W1[2 * HID + j]
                + relS[r][3] * W1[3 * HID + j];
        h1s[r][j] = geluf(a);
    }
    __syncthreads();

    int c = tid;  // output column, 0..255

    // ---- stage A: h2 = h1 @ W2 + b2  (K=64), float4 LDS on x ----
    {
        float a0 = 0.f, a1 = 0.f, a2 = 0.f, a3 = 0.f;
        #pragma unroll
        for (int k = 0; k < HID; k += 4) {
            float4 x0 = *(const float4*)&h1s[0][k];
            float4 x1 = *(const float4*)&h1s[1][k];
            float4 x2 = *(const float4*)&h1s[2][k];
            float4 x3 = *(const float4*)&h1s[3][k];
            #pragma unroll
            for (int kk = 0; kk < 4; kk++) {
                float wv = __ldg(W2 + (k + kk) * DD + c);
                a0 += (&x0.x)[kk] * wv; a1 += (&x1.x)[kk] * wv;
                a2 += (&x2.x)[kk] * wv; a3 += (&x3.x)[kk] * wv;
            }
        }
        float bv = b2[c];
        h2s[0][c] = a0 + bv; h2s[1][c] = a1 + bv;
        h2s[2][c] = a2 + bv; h2s[3][c] = a3 + bv;
    }
    __syncthreads();

    // ---- stage B: a3 = h2 @ W3 + b3  (K=256) -> registers, float4 LDS on x ----
    float v0, v1, v2, v3;
    {
        float a0 = 0.f, a1 = 0.f, a2 = 0.f, a3 = 0.f;
        #pragma unroll 8
        for (int k = 0; k < DD; k += 4) {
            float4 x0 = *(const float4*)&h2s[0][k];
            float4 x1 = *(const float4*)&h2s[1][k];
            float4 x2 = *(const float4*)&h2s[2][k];
            float4 x3 = *(const float4*)&h2s[3][k];
            #pragma unroll
            for (int kk = 0; kk < 4; kk++) {
                float wv = __ldg(W3 + (k + kk) * DD + c);
                a0 += (&x0.x)[kk] * wv; a1 += (&x1.x)[kk] * wv;
                a2 += (&x2.x)[kk] * wv; a3 += (&x3.x)[kk] * wv;
            }
        }
        float bv = b3[c];
        v0 = a0 + bv; v1 = a1 + bv; v2 = a2 + bv; v3 = a3 + bv;
    }

    // ---- layernorm (per row over 256 cols) + gelu ----
    {
        float s0 = v0, s1 = v1, s2 = v2, s3 = v3;
        #pragma unroll
        for (int o = 16; o > 0; o >>= 1) {
            s0 += __shfl_xor_sync(0xffffffffu, s0, o);
            s1 += __shfl_xor_sync(0xffffffffu, s1, o);
            s2 += __shfl_xor_sync(0xffffffffu, s2, o);
            s3 += __shfl_xor_sync(0xffffffffu, s3, o);
        }
        if (lane == 0) { red[w*4+0]=s0; red[w*4+1]=s1; red[w*4+2]=s2; red[w*4+3]=s3; }
    }
    __syncthreads();
    float m0=0,m1=0,m2=0,m3=0;
    #pragma unroll
    for (int i = 0; i < 8; i++) { m0+=red[i*4+0]; m1+=red[i*4+1]; m2+=red[i*4+2]; m3+=red[i*4+3]; }
    m0 *= (1.0f/DD); m1 *= (1.0f/DD); m2 *= (1.0f/DD); m3 *= (1.0f/DD);
    __syncthreads();
    float d0 = v0-m0, d1 = v1-m1, d2 = v2-m2, d3 = v3-m3;
    {
        float s0 = d0*d0, s1 = d1*d1, s2 = d2*d2, s3 = d3*d3;
        #pragma unroll
        for (int o = 16; o > 0; o >>= 1) {
            s0 += __shfl_xor_sync(0xffffffffu, s0, o);
            s1 += __shfl_xor_sync(0xffffffffu, s1, o);
            s2 += __shfl_xor_sync(0xffffffffu, s2, o);
            s3 += __shfl_xor_sync(0xffffffffu, s3, o);
        }
        if (lane == 0) { red[w*4+0]=s0; red[w*4+1]=s1; red[w*4+2]=s2; red[w*4+3]=s3; }
    }
    __syncthreads();
    float q0=0,q1=0,q2=0,q3=0;
    #pragma unroll
    for (int i = 0; i < 8; i++) { q0+=red[i*4+0]; q1+=red[i*4+1]; q2+=red[i*4+2]; q3+=red[i*4+3]; }
    float g = lng[c], bb = lnb[c];
    ys[0][c] = geluf(d0 * rsqrtf(q0*(1.0f/DD) + 1e-5f) * g + bb);
    ys[1][c] = geluf(d1 * rsqrtf(q1*(1.0f/DD) + 1e-5f) * g + bb);
    ys[2][c] = geluf(d2 * rsqrtf(q2*(1.0f/DD) + 1e-5f) * g + bb);
    ys[3][c] = geluf(d3 * rsqrtf(q3*(1.0f/DD) + 1e-5f) * g + bb);
    __syncthreads();

    // ---- stage C: a4 = (y @ W4 + b4) * mask -> g_a4, float4 LDS on x ----
    {
        float a0 = 0.f, a1 = 0.f, a2 = 0.f, a3 = 0.f;
        #pragma unroll 8
        for (int k = 0; k < DD; k += 4) {
            float4 x0 = *(const float4*)&ys[0][k];
            float4 x1 = *(const float4*)&ys[1][k];
            float4 x2 = *(const float4*)&ys[2][k];
            float4 x3 = *(const float4*)&ys[3][k];
            #pragma unroll
            for (int kk = 0; kk < 4; kk++) {
                float wv = __ldg(W4 + (k + kk) * DD + c);
                a0 += (&x0.x)[kk] * wv; a1 += (&x1.x)[kk] * wv;
                a2 += (&x2.x)[kk] * wv; a3 += (&x3.x)[kk] * wv;
            }
        }
        float bv = b4[c];
        float* out = g_a4 + ((long long)b * SS + r0) * DD + c;
        out[0 * DD] = (a0 + bv) * maskS[0];
        out[1 * DD] = (a1 + bv) * maskS[1];
        out[2 * DD] = (a2 + bv) * maskS[2];
        out[3 * DD] = (a3 + bv) * maskS[3];
    }
}

// ---------------- K3: gather epilogue (HBM-write-bound roofline) ----------------
// Plain write-back stores: let dirty lines linger in L2 and drain during the
// next replay's accum/middle window (which is DRAM-idle).
__global__ void gather_kernel(const int* __restrict__ labels, float4* __restrict__ out) {
    int b   = blockIdx.y;
    int idx = blockIdx.x * 256 + threadIdx.x;   // 0 .. NN*32-1 (exact, 5000 blocks)
    int pt  = idx >> 5;                         // point within batch
    int c4  = idx & 31;
    int lab = __ldg(labels + b * NN + pt) & (SS - 1);
    const float4* row = (const float4*)(g_a4 + (long long)(b * SS + lab) * DD);
    float4 u0 = __ldg(row + c4);
    float4 u1 = __ldg(row + c4 + 32);
    float4* o = out + ((long long)b * NN + pt) * (DD / 4);
    o[c4]      = u0;
    o[c4 + 32] = u1;
}

// ---------------- launch ----------------
extern "C" void kernel_launch(void* const* d_in, const int* in_sizes, int n_in,
                              void* d_out, int out_size) {
    const float* coords = (const float*)d_in[0];
    // d_in[1] = features (unused), d_in[3] = num_superpoints (compile-time 128)
    const int*   labels = (const int*)d_in[2];
    const float* W1  = (const float*)d_in[4];
    const float* b1  = (const float*)d_in[5];
    const float* W2  = (const float*)d_in[6];
    const float* b2  = (const float*)d_in[7];
    const float* W3  = (const float*)d_in[8];
    const float* b3  = (const float*)d_in[9];
    const float* lng = (const float*)d_in[10];
    const float* lnb = (const float*)d_in[11];
    const float* W4  = (const float*)d_in[12];
    const float* b4  = (const float*)d_in[13];

    accum_kernel<<<dim3(NACC, BB), 256>>>(coords, labels);
    middle_kernel<<<dim3(SS / RPB, BB), 256>>>(W1, b1, W2, b2, W3, b3, lng, lnb, W4, b4);
    gather_kernel<<<dim3((NN * 32) / 256, BB), 256>>>(labels, (float4*)d_out);
}

// round 15
// speedup vs baseline: 1.3813x; 1.3813x over previous
#include <cuda_runtime.h>
#include <math.h>

#define BB   8
#define NN   40000
#define DD   256
#define SS   128
#define HID  64
#define RPB  4          // rows per block in fused middle kernel
#define NACC 72         // accumulation blocks per batch
#define PTS  556        // points per accum block (72*556 = 40032 >= 40000)

// ---------------- device scratch (no allocations allowed) ----------------
__device__ long long g_p1[BB * NACC * SS];   // packed (cnt, z) partials
__device__ long long g_p2[BB * NACC * SS];   // packed (x, y) partials
__device__ float     g_a4[BB * SS * DD];     // final per-superpoint table (masked)

__device__ __forceinline__ float geluf(float x) { return x * normcdff(x); }

// ---------------- K1: segment accumulation, 2 packed smem atomics per point ----------------
// Fixed point scale 2^17. A1 = cnt*2^32 + (z17 + 2^31); A2 = x17*2^32 + (y17 + 2^31).
// 4-way replicated histograms (warp & 3) to cut smem-atomic conflict degree.
__global__ __launch_bounds__(256) void accum_kernel(const float* __restrict__ coords,
                                                    const int* __restrict__ labels) {
    __shared__ unsigned long long s1[4][SS], s2[4][SS];
    int b = blockIdx.y;
    int j = blockIdx.x;
    int base = j * PTS;
    int tid = threadIdx.x;
    int rep = (tid >> 5) & 3;

    for (int i = tid; i < 4 * SS; i += 256) {
        ((unsigned long long*)s1)[i] = 0ULL;
        ((unsigned long long*)s2)[i] = 0ULL;
    }
    __syncthreads();

    const float SC = 131072.0f; // 2^17
    #pragma unroll 3
    for (int i = tid; i < PTS; i += 256) {
        int n = base + i;
        if (n < NN) {
            long long pt = (long long)b * NN + n;
            int lab = __ldg(labels + pt) & (SS - 1);
            const float* c = coords + pt * 3;
            float fx = __ldg(c + 0), fy = __ldg(c + 1), fz = __ldg(c + 2);
            long long x17 = __float2int_rn(fx * SC);
            long long y17 = __float2int_rn(fy * SC);
            long long z17 = __float2int_rn(fz * SC);
            unsigned long long a1 = (unsigned long long)((1LL << 32) + (1LL << 31) + z17);
            unsigned long long a2 = (unsigned long long)((x17 << 32) + (1LL << 31) + y17);
            atomicAdd(&s1[rep][lab], a1);
            atomicAdd(&s2[rep][lab], a2);
        }
    }
    __syncthreads();

    if (tid < SS) {
        unsigned long long t1 = s1[0][tid] + s1[1][tid] + s1[2][tid] + s1[3][tid];
        unsigned long long t2 = s2[0][tid] + s2[1][tid] + s2[2][tid] + s2[3][tid];
        g_p1[(b * NACC + j) * SS + tid] = (long long)t1;
        g_p2[(b * NACC + j) * SS + tid] = (long long)t2;
    }
}

// ---------------- K2: fully fused middle (centers -> rel -> MLP -> LN -> a4) ----------------
__global__ __launch_bounds__(256) void middle_kernel(
    const float* __restrict__ W1, const float* __restrict__ b1,
    const float* __restrict__ W2, const float* __restrict__ b2,
    const float* __restrict__ W3, const float* __restrict__ b3,
    const float* __restrict__ lng, const float* __restrict__ lnb,
    const float* __restrict__ W4, const float* __restrict__ b4)
{
    int b   = blockIdx.y;
    int r0  = blockIdx.x * RPB;
    int tid = threadIdx.x;
    int lane = tid & 31, w = tid >> 5;

    __shared__ float cx[SS], cy[SS], cz[SS], vm[SS];
    __shared__ float relS[RPB][4];
    __shared__ float maskS[RPB];
    __shared__ __align__(16) float h1s[RPB][HID];
    __shared__ __align__(16) float h2s[RPB][DD];
    __shared__ __align__(16) float ys [RPB][DD];
    __shared__ float red[8 * RPB];
    __shared__ float s_nv;

    // ---- reduce packed partials -> centers for ALL superpoints of this batch ----
    if (tid < SS) {
        long long v1 = 0, v2 = 0;
        #pragma unroll 8
        for (int j = 0; j < NACC; j++) {
            v1 += g_p1[(b * NACC + j) * SS + tid];
            v2 += g_p2[(b * NACC + j) * SS + tid];
        }
        const long long T31 = 3LL << 31;
        long long cnt = (v1 + (T31 >> 1)) / T31;        // V1 = cnt*3*2^31 + z_sum
        long long zs  = v1 - cnt * T31;
        long long u   = v2 - (cnt << 31);               // = x_sum*2^32 + y_sum
        int  ylow = (int)(unsigned int)(u & 0xFFFFFFFFULL);
        long long xs = (u - (long long)ylow) >> 32;

        float cf = (float)cnt;
        float dc = fmaxf(cf, 1.0f);
        const float INV = 1.0f / 131072.0f;
        cx[tid] = ((float)xs   * INV) / dc;
        cy[tid] = ((float)ylow * INV) / dc;
        cz[tid] = ((float)zs   * INV) / dc;
        vm[tid] = (cf >= 2.0f) ? 1.0f : 0.0f;
    }
    __syncthreads();
    if (tid == 0) {
        float t = 0.f;
        #pragma unroll 8
        for (int i = 0; i < SS; i++) t += vm[i];
        s_nv = t;
    }
    __syncthreads();
    float nv    = s_nv;
    float denom = fmaxf(nv, 1.0f);

    // ---- rel features: warp r (0..3) handles row r0+r ----
    if (w < RPB) {
        int s = r0 + w;
        float xs = cx[s], ysv = cy[s], zs = cz[s];
        float msum = 0.f, mind = INFINITY, fcnt = 0.f;
        #pragma unroll
        for (int t = lane; t < SS; t += 32) {
            float dx = xs - cx[t], dy = ysv - cy[t], dz = zs - cz[t];
            float d2 = dx * dx + dy * dy + dz * dz;
            float dist = (d2 > 0.f) ? sqrtf(d2) : 0.f;
            float v = vm[t];
            msum += dist * v;
            if (v > 0.f) mind = fminf(mind, dist);
            fcnt += (zs > cz[t] ? 1.0f : 0.0f) * v;
        }
        #pragma unroll
        for (int o = 16; o > 0; o >>= 1) {
            msum += __shfl_xor_sync(0xffffffffu, msum, o);
            mind  = fminf(mind, __shfl_xor_sync(0xffffffffu, mind, o));
            fcnt += __shfl_xor_sync(0xffffffffu, fcnt, o);
        }
        if (lane == 0) {
            relS[w][0] = msum / denom;
            relS[w][1] = mind;
            relS[w][2] = zs;
            relS[w][3] = fcnt / denom;
            maskS[w]   = vm[s] * ((nv >= 2.0f) ? 1.0f : 0.0f);
        }
    }
    __syncthreads();

    // ---- h1 = gelu(rel @ W1 + b1): tid -> (r = tid>>6, j = tid&63) ----
    {
        int r = tid >> 6, j = tid & 63;
        float a = b1[j]
                + relS[r][0] * W1[0 * HID + j]
                + relS[r][1] * W1[1 * HID + j]
                + relS[r][2] * W1[2 * HID + j]
                + relS[r][3] * W1[3 * HID + j];
        h1s[r][j] = geluf(a);
    }
    __syncthreads();

    int c = tid;  // output column, 0..255

    // ---- stage A: h2 = h1 @ W2 + b2  (K=64), float4 LDS on x ----
    {
        float a0 = 0.f, a1 = 0.f, a2 = 0.f, a3 = 0.f;
        #pragma unroll
        for (int k = 0; k < HID; k += 4) {
            float4 x0 = *(const float4*)&h1s[0][k];
            float4 x1 = *(const float4*)&h1s[1][k];
            float4 x2 = *(const float4*)&h1s[2][k];
            float4 x3 = *(const float4*)&h1s[3][k];
            #pragma unroll
            for (int kk = 0; kk < 4; kk++) {
                float wv = __ldg(W2 + (k + kk) * DD + c);
                a0 += (&x0.x)[kk] * wv; a1 += (&x1.x)[kk] * wv;
                a2 += (&x2.x)[kk] * wv; a3 += (&x3.x)[kk] * wv;
            }
        }
        float bv = b2[c];
        h2s[0][c] = a0 + bv; h2s[1][c] = a1 + bv;
        h2s[2][c] = a2 + bv; h2s[3][c] = a3 + bv;
    }
    __syncthreads();

    // ---- stage B: a3 = h2 @ W3 + b3  (K=256) -> registers, float4 LDS on x ----
    float v0, v1, v2, v3;
    {
        float a0 = 0.f, a1 = 0.f, a2 = 0.f, a3 = 0.f;
        #pragma unroll 8
        for (int k = 0; k < DD; k += 4) {
            float4 x0 = *(const float4*)&h2s[0][k];
            float4 x1 = *(const float4*)&h2s[1][k];
            float4 x2 = *(const float4*)&h2s[2][k];
            float4 x3 = *(const float4*)&h2s[3][k];
            #pragma unroll
            for (int kk = 0; kk < 4; kk++) {
                float wv = __ldg(W3 + (k + kk) * DD + c);
                a0 += (&x0.x)[kk] * wv; a1 += (&x1.x)[kk] * wv;
                a2 += (&x2.x)[kk] * wv; a3 += (&x3.x)[kk] * wv;
            }
        }
        float bv = b3[c];
        v0 = a0 + bv; v1 = a1 + bv; v2 = a2 + bv; v3 = a3 + bv;
    }

    // ---- layernorm (per row over 256 cols) + gelu ----
    {
        float s0 = v0, s1 = v1, s2 = v2, s3 = v3;
        #pragma unroll
        for (int o = 16; o > 0; o >>= 1) {
            s0 += __shfl_xor_sync(0xffffffffu, s0, o);
            s1 += __shfl_xor_sync(0xffffffffu, s1, o);
            s2 += __shfl_xor_sync(0xffffffffu, s2, o);
            s3 += __shfl_xor_sync(0xffffffffu, s3, o);
        }
        if (lane == 0) { red[w*4+0]=s0; red[w*4+1]=s1; red[w*4+2]=s2; red[w*4+3]=s3; }
    }
    __syncthreads();
    float m0=0,m1=0,m2=0,m3=0;
    #pragma unroll
    for (int i = 0; i < 8; i++) { m0+=red[i*4+0]; m1+=red[i*4+1]; m2+=red[i*4+2]; m3+=red[i*4+3]; }
    m0 *= (1.0f/DD); m1 *= (1.0f/DD); m2 *= (1.0f/DD); m3 *= (1.0f/DD);
    __syncthreads();
    float d0 = v0-m0, d1 = v1-m1, d2 = v2-m2, d3 = v3-m3;
    {
        float s0 = d0*d0, s1 = d1*d1, s2 = d2*d2, s3 = d3*d3;
        #pragma unroll
        for (int o = 16; o > 0; o >>= 1) {
            s0 += __shfl_xor_sync(0xffffffffu, s0, o);
            s1 += __shfl_xor_sync(0xffffffffu, s1, o);
            s2 += __shfl_xor_sync(0xffffffffu, s2, o);
            s3 += __shfl_xor_sync(0xffffffffu, s3, o);
        }
        if (lane == 0) { red[w*4+0]=s0; red[w*4+1]=s1; red[w*4+2]=s2; red[w*4+3]=s3; }
    }
    __syncthreads();
    float q0=0,q1=0,q2=0,q3=0;
    #pragma unroll
    for (int i = 0; i < 8; i++) { q0+=red[i*4+0]; q1+=red[i*4+1]; q2+=red[i*4+2]; q3+=red[i*4+3]; }
    float g = lng[c], bb = lnb[c];
    ys[0][c] = geluf(d0 * rsqrtf(q0*(1.0f/DD) + 1e-5f) * g + bb);
    ys[1][c] = geluf(d1 * rsqrtf(q1*(1.0f/DD) + 1e-5f) * g + bb);
    ys[2][c] = geluf(d2 * rsqrtf(q2*(1.0f/DD) + 1e-5f) * g + bb);
    ys[3][c] = geluf(d3 * rsqrtf(q3*(1.0f/DD) + 1e-5f) * g + bb);
    __syncthreads();

    // ---- stage C: a4 = (y @ W4 + b4) * mask -> g_a4, float4 LDS on x ----
    {
        float a0 = 0.f, a1 = 0.f, a2 = 0.f, a3 = 0.f;
        #pragma unroll 8
        for (int k = 0; k < DD; k += 4) {
            float4 x0 = *(const float4*)&ys[0][k];
            float4 x1 = *(const float4*)&ys[1][k];
            float4 x2 = *(const float4*)&ys[2][k];
            float4 x3 = *(const float4*)&ys[3][k];
            #pragma unroll
            for (int kk = 0; kk < 4; kk++) {
                float wv = __ldg(W4 + (k + kk) * DD + c);
                a0 += (&x0.x)[kk] * wv; a1 += (&x1.x)[kk] * wv;
                a2 += (&x2.x)[kk] * wv; a3 += (&x3.x)[kk] * wv;
            }
        }
        float bv = b4[c];
        float* out = g_a4 + ((long long)b * SS + r0) * DD + c;
        out[0 * DD] = (a0 + bv) * maskS[0];
        out[1 * DD] = (a1 + bv) * maskS[1];
        out[2 * DD] = (a2 + bv) * maskS[2];
        out[3 * DD] = (a3 + bv) * maskS[3];
    }
}

// ---------------- K3: gather epilogue (HBM-write-bound roofline) ----------------
// __stcs streaming stores are load-bearing: plain write-back thrashes L2 (+34us, R14).
__global__ void gather_kernel(const int* __restrict__ labels, float4* __restrict__ out) {
    int b   = blockIdx.y;
    int idx = blockIdx.x * 256 + threadIdx.x;   // 0 .. NN*32-1 (exact, 5000 blocks)
    int pt  = idx >> 5;                         // point within batch
    int c4  = idx & 31;
    int lab = __ldg(labels + b * NN + pt) & (SS - 1);
    const float4* row = (const float4*)(g_a4 + (long long)(b * SS + lab) * DD);
    float4 u0 = __ldg(row + c4);
    float4 u1 = __ldg(row + c4 + 32);
    float4* o = out + ((long long)b * NN + pt) * (DD / 4);
    __stcs(o + c4,      u0);
    __stcs(o + c4 + 32, u1);
}

// ---------------- launch ----------------
extern "C" void kernel_launch(void* const* d_in, const int* in_sizes, int n_in,
                              void* d_out, int out_size) {
    const float* coords = (const float*)d_in[0];
    // d_in[1] = features (unused), d_in[3] = num_superpoints (compile-time 128)
    const int*   labels = (const int*)d_in[2];
    const float* W1  = (const float*)d_in[4];
    const float* b1  = (const float*)d_in[5];
    const float* W2  = (const float*)d_in[6];
    const float* b2  = (const float*)d_in[7];
    const float* W3  = (const float*)d_in[8];
    const float* b3  = (const float*)d_in[9];
    const float* lng = (const float*)d_in[10];
    const float* lnb = (const float*)d_in[11];
    const float* W4  = (const float*)d_in[12];
    const float* b4  = (const float*)d_in[13];

    accum_kernel<<<dim3(NACC, BB), 256>>>(coords, labels);
    middle_kernel<<<dim3(SS / RPB, BB), 256>>>(W1, b1, W2, b2, W3, b3, lng, lnb, W4, b4);
    gather_kernel<<<dim3((NN * 32) / 256, BB), 256>>>(labels, (float4*)d_out);
}

// round 16
// speedup vs baseline: 1.4226x; 1.0299x over previous
#include <cuda_runtime.h>
#include <math.h>

#define BB   8
#define NN   40000
#define DD   256
#define SS   128
#define HID  64
#define RPB  4          // rows per block in fused middle kernel
#define NACC 40         // accumulation blocks per batch
#define PTS  1000       // points per accum block (40*1000 = 40000 exactly)

// ---------------- device scratch (no allocations allowed) ----------------
__device__ long long g_p1[BB * NACC * SS];   // packed (cnt, z) partials
__device__ long long g_p2[BB * NACC * SS];   // packed (x, y) partials
__device__ float     g_a4[BB * SS * DD];     // final per-superpoint table (masked)

__device__ __forceinline__ float geluf(float x) { return x * normcdff(x); }

// ---------------- K1: segment accumulation, vectorized front end ----------------
// Fixed point scale 2^17. A1 = cnt*2^32 + (z17 + 2^31); A2 = x17*2^32 + (y17 + 2^31).
// Each thread owns 4 consecutive points: 1 int4 + 3 float4 loads (16B aligned).
// 2-way replicated histograms (warp parity).
__global__ __launch_bounds__(256) void accum_kernel(const float* __restrict__ coords,
                                                    const int* __restrict__ labels) {
    __shared__ unsigned long long s1[2][SS], s2[2][SS];
    int b = blockIdx.y;
    int j = blockIdx.x;
    int tid = threadIdx.x;
    int rep = (tid >> 5) & 1;

    for (int i = tid; i < 2 * SS; i += 256) {
        ((unsigned long long*)s1)[i] = 0ULL;
        ((unsigned long long*)s2)[i] = 0ULL;
    }
    __syncthreads();

    const float SC = 131072.0f; // 2^17
    if (tid < PTS / 4) {
        long long pt = (long long)b * NN + j * PTS + tid * 4;
        int4  lb = __ldg((const int4*)(labels + pt));
        const float* cp = coords + pt * 3;
        float4 c0 = __ldg((const float4*)(cp + 0));
        float4 c1 = __ldg((const float4*)(cp + 4));
        float4 c2 = __ldg((const float4*)(cp + 8));

        float px[4] = {c0.x, c0.w, c1.z, c2.y};
        float py[4] = {c0.y, c1.x, c1.w, c2.z};
        float pz[4] = {c0.z, c1.y, c2.x, c2.w};
        int   pl[4] = {lb.x, lb.y, lb.z, lb.w};

        #pragma unroll
        for (int q = 0; q < 4; q++) {
            int lab = pl[q] & (SS - 1);
            long long x17 = __float2int_rn(px[q] * SC);
            long long y17 = __float2int_rn(py[q] * SC);
            long long z17 = __float2int_rn(pz[q] * SC);
            unsigned long long a1 = (unsigned long long)((1LL << 32) + (1LL << 31) + z17);
            unsigned long long a2 = (unsigned long long)((x17 << 32) + (1LL << 31) + y17);
            atomicAdd(&s1[rep][lab], a1);
            atomicAdd(&s2[rep][lab], a2);
        }
    }
    __syncthreads();

    if (tid < SS) {
        g_p1[(b * NACC + j) * SS + tid] = (long long)(s1[0][tid] + s1[1][tid]);
        g_p2[(b * NACC + j) * SS + tid] = (long long)(s2[0][tid] + s2[1][tid]);
    }
}

// ---------------- K2: fully fused middle (centers -> rel -> MLP -> LN -> a4) ----------------
__global__ __launch_bounds__(256) void middle_kernel(
    const float* __restrict__ W1, const float* __restrict__ b1,
    const float* __restrict__ W2, const float* __restrict__ b2,
    const float* __restrict__ W3, const float* __restrict__ b3,
    const float* __restrict__ lng, const float* __restrict__ lnb,
    const float* __restrict__ W4, const float* __restrict__ b4)
{
    int b   = blockIdx.y;
    int r0  = blockIdx.x * RPB;
    int tid = threadIdx.x;
    int lane = tid & 31, w = tid >> 5;

    __shared__ float cx[SS], cy[SS], cz[SS], vm[SS];
    __shared__ float relS[RPB][4];
    __shared__ float maskS[RPB];
    __shared__ __align__(16) float h1s[RPB][HID];
    __shared__ __align__(16) float h2s[RPB][DD];
    __shared__ __align__(16) float ys [RPB][DD];
    __shared__ float red[8 * RPB];
    __shared__ float s_nv;

    // ---- reduce packed partials -> centers for ALL superpoints of this batch ----
    if (tid < SS) {
        long long v1 = 0, v2 = 0;
        #pragma unroll 8
        for (int j = 0; j < NACC; j++) {
            v1 += g_p1[(b * NACC + j) * SS + tid];
            v2 += g_p2[(b * NACC + j) * SS + tid];
        }
        const long long T31 = 3LL << 31;
        long long cnt = (v1 + (T31 >> 1)) / T31;        // V1 = cnt*3*2^31 + z_sum
        long long zs  = v1 - cnt * T31;
        long long u   = v2 - (cnt << 31);               // = x_sum*2^32 + y_sum
        int  ylow = (int)(unsigned int)(u & 0xFFFFFFFFULL);
        long long xs = (u - (long long)ylow) >> 32;

        float cf = (float)cnt;
        float dc = fmaxf(cf, 1.0f);
        const float INV = 1.0f / 131072.0f;
        cx[tid] = ((float)xs   * INV) / dc;
        cy[tid] = ((float)ylow * INV) / dc;
        cz[tid] = ((float)zs   * INV) / dc;
        vm[tid] = (cf >= 2.0f) ? 1.0f : 0.0f;
    }
    __syncthreads();
    if (tid == 0) {
        float t = 0.f;
        #pragma unroll 8
        for (int i = 0; i < SS; i++) t += vm[i];
        s_nv = t;
    }
    __syncthreads();
    float nv    = s_nv;
    float denom = fmaxf(nv, 1.0f);

    // ---- rel features: warp r (0..3) handles row r0+r ----
    if (w < RPB) {
        int s = r0 + w;
        float xs = cx[s], ysv = cy[s], zs = cz[s];
        float msum = 0.f, mind = INFINITY, fcnt = 0.f;
        #pragma unroll
        for (int t = lane; t < SS; t += 32) {
            float dx = xs - cx[t], dy = ysv - cy[t], dz = zs - cz[t];
            float d2 = dx * dx + dy * dy + dz * dz;
            float dist = (d2 > 0.f) ? sqrtf(d2) : 0.f;
            float v = vm[t];
            msum += dist * v;
            if (v > 0.f) mind = fminf(mind, dist);
            fcnt += (zs > cz[t] ? 1.0f : 0.0f) * v;
        }
        #pragma unroll
        for (int o = 16; o > 0; o >>= 1) {
            msum += __shfl_xor_sync(0xffffffffu, msum, o);
            mind  = fminf(mind, __shfl_xor_sync(0xffffffffu, mind, o));
            fcnt += __shfl_xor_sync(0xffffffffu, fcnt, o);
        }
        if (lane == 0) {
            relS[w][0] = msum / denom;
            relS[w][1] = mind;
            relS[w][2] = zs;
            relS[w][3] = fcnt / denom;
            maskS[w]   = vm[s] * ((nv >= 2.0f) ? 1.0f : 0.0f);
        }
    }
    __syncthreads();

    // ---- h1 = gelu(rel @ W1 + b1): tid -> (r = tid>>6, j = tid&63) ----
    {
        int r = tid >> 6, j = tid & 63;
        float a = b1[j]
                + relS[r][0] * W1[0 * HID + j]
                + relS[r][1] * W1[1 * HID + j]
                + relS[r][2] * W1[2 * HID + j]
                + relS[r][3] * W1[3 * HID + j];
        h1s[r][j] = geluf(a);
    }
    __syncthreads();

    int c = tid;  // output column, 0..255

    // ---- stage A: h2 = h1 @ W2 + b2  (K=64), float4 LDS on x ----
    {
        float a0 = 0.f, a1 = 0.f, a2 = 0.f, a3 = 0.f;
        #pragma unroll
        for (int k = 0; k < HID; k += 4) {
            float4 x0 = *(const float4*)&h1s[0][k];
            float4 x1 = *(const float4*)&h1s[1][k];
            float4 x2 = *(const float4*)&h1s[2][k];
            float4 x3 = *(const float4*)&h1s[3][k];
            #pragma unroll
            for (int kk = 0; kk < 4; kk++) {
                float wv = __ldg(W2 + (k + kk) * DD + c);
                a0 += (&x0.x)[kk] * wv; a1 += (&x1.x)[kk] * wv;
                a2 += (&x2.x)[kk] * wv; a3 += (&x3.x)[kk] * wv;
            }
        }
        float bv = b2[c];
        h2s[0][c] = a0 + bv; h2s[1][c] = a1 + bv;
        h2s[2][c] = a2 + bv; h2s[3][c] = a3 + bv;
    }
    __syncthreads();

    // ---- stage B: a3 = h2 @ W3 + b3  (K=256) -> registers, float4 LDS on x ----
    float v0, v1, v2, v3;
    {
        float a0 = 0.f, a1 = 0.f, a2 = 0.f, a3 = 0.f;
        #pragma unroll 8
        for (int k = 0; k < DD; k += 4) {
            float4 x0 = *(const float4*)&h2s[0][k];
            float4 x1 = *(const float4*)&h2s[1][k];
            float4 x2 = *(const float4*)&h2s[2][k];
            float4 x3 = *(const float4*)&h2s[3][k];
            #pragma unroll
            for (int kk = 0; kk < 4; kk++) {
                float wv = __ldg(W3 + (k + kk) * DD + c);
                a0 += (&x0.x)[kk] * wv; a1 += (&x1.x)[kk] * wv;
                a2 += (&x2.x)[kk] * wv; a3 += (&x3.x)[kk] * wv;
            }
        }
        float bv = b3[c];
        v0 = a0 + bv; v1 = a1 + bv; v2 = a2 + bv; v3 = a3 + bv;
    }

    // ---- layernorm (per row over 256 cols) + gelu ----
    {
        float s0 = v0, s1 = v1, s2 = v2, s3 = v3;
        #pragma unroll
        for (int o = 16; o > 0; o >>= 1) {
            s0 += __shfl_xor_sync(0xffffffffu, s0, o);
            s1 += __shfl_xor_sync(0xffffffffu, s1, o);
            s2 += __shfl_xor_sync(0xffffffffu, s2, o);
            s3 += __shfl_xor_sync(0xffffffffu, s3, o);
        }
        if (lane == 0) { red[w*4+0]=s0; red[w*4+1]=s1; red[w*4+2]=s2; red[w*4+3]=s3; }
    }
    __syncthreads();
    float m0=0,m1=0,m2=0,m3=0;
    #pragma unroll
    for (int i = 0; i < 8; i++) { m0+=red[i*4+0]; m1+=red[i*4+1]; m2+=red[i*4+2]; m3+=red[i*4+3]; }
    m0 *= (1.0f/DD); m1 *= (1.0f/DD); m2 *= (1.0f/DD); m3 *= (1.0f/DD);
    __syncthreads();
    float d0 = v0-m0, d1 = v1-m1, d2 = v2-m2, d3 = v3-m3;
    {
        float s0 = d0*d0, s1 = d1*d1, s2 = d2*d2, s3 = d3*d3;
        #pragma unroll
        for (int o = 16; o > 0; o >>= 1) {
            s0 += __shfl_xor_sync(0xffffffffu, s0, o);
            s1 += __shfl_xor_sync(0xffffffffu, s1, o);
            s2 += __shfl_xor_sync(0xffffffffu, s2, o);
            s3 += __shfl_xor_sync(0xffffffffu, s3, o);
        }
        if (lane == 0) { red[w*4+0]=s0; red[w*4+1]=s1; red[w*4+2]=s2; red[w*4+3]=s3; }
    }
    __syncthreads();
    float q0=0,q1=0,q2=0,q3=0;
    #pragma unroll
    for (int i = 0; i < 8; i++) { q0+=red[i*4+0]; q1+=red[i*4+1]; q2+=red[i*4+2]; q3+=red[i*4+3]; }
    float g = lng[c], bb = lnb[c];
    ys[0][c] = geluf(d0 * rsqrtf(q0*(1.0f/DD) + 1e-5f) * g + bb);
    ys[1][c] = geluf(d1 * rsqrtf(q1*(1.0f/DD) + 1e-5f) * g + bb);
    ys[2][c] = geluf(d2 * rsqrtf(q2*(1.0f/DD) + 1e-5f) * g + bb);
    ys[3][c] = geluf(d3 * rsqrtf(q3*(1.0f/DD) + 1e-5f) * g + bb);
    __syncthreads();

    // ---- stage C: a4 = (y @ W4 + b4) * mask -> g_a4, float4 LDS on x ----
    {
        float a0 = 0.f, a1 = 0.f, a2 = 0.f, a3 = 0.f;
        #pragma unroll 8
        for (int k = 0; k < DD; k += 4) {
            float4 x0 = *(const float4*)&ys[0][k];
            float4 x1 = *(const float4*)&ys[1][k];
            float4 x2 = *(const float4*)&ys[2][k];
            float4 x3 = *(const float4*)&ys[3][k];
            #pragma unroll
            for (int kk = 0; kk < 4; kk++) {
                float wv = __ldg(W4 + (k + kk) * DD + c);
                a0 += (&x0.x)[kk] * wv; a1 += (&x1.x)[kk] * wv;
                a2 += (&x2.x)[kk] * wv; a3 += (&x3.x)[kk] * wv;
            }
        }
        float bv = b4[c];
        float* out = g_a4 + ((long long)b * SS + r0) * DD + c;
        out[0 * DD] = (a0 + bv) * maskS[0];
        out[1 * DD] = (a1 + bv) * maskS[1];
        out[2 * DD] = (a2 + bv) * maskS[2];
        out[3 * DD] = (a3 + bv) * maskS[3];
    }
}

// ---------------- K3: gather epilogue (HBM-write-bound roofline) ----------------
// __stcs streaming stores are load-bearing: plain write-back thrashes L2 (+34us, R14).
__global__ void gather_kernel(const int* __restrict__ labels, float4* __restrict__ out) {
    int b   = blockIdx.y;
    int idx = blockIdx.x * 256 + threadIdx.x;   // 0 .. NN*32-1 (exact, 5000 blocks)
    int pt  = idx >> 5;                         // point within batch
    int c4  = idx & 31;
    int lab = __ldg(labels + b * NN + pt) & (SS - 1);
    const float4* row = (const float4*)(g_a4 + (long long)(b * SS + lab) * DD);
    float4 u0 = __ldg(row + c4);
    float4 u1 = __ldg(row + c4 + 32);
    float4* o = out + ((long long)b * NN + pt) * (DD / 4);
    __stcs(o + c4,      u0);
    __stcs(o + c4 + 32, u1);
}

// ---------------- launch ----------------
extern "C" void kernel_launch(void* const* d_in, const int* in_sizes, int n_in,
                              void* d_out, int out_size) {
    const float* coords = (const float*)d_in[0];
    // d_in[1] = features (unused), d_in[3] = num_superpoints (compile-time 128)
    const int*   labels = (const int*)d_in[2];
    const float* W1  = (const float*)d_in[4];
    const float* b1  = (const float*)d_in[5];
    const float* W2  = (const float*)d_in[6];
    const float* b2  = (const float*)d_in[7];
    const float* W3  = (const float*)d_in[8];
    const float* b3  = (const float*)d_in[9];
    const float* lng = (const float*)d_in[10];
    const float* lnb = (const float*)d_in[11];
    const float* W4  = (const float*)d_in[12];
    const float* b4  = (const float*)d_in[13];

    accum_kernel<<<dim3(NACC, BB), 256>>>(coords, labels);
    middle_kernel<<<dim3(SS / RPB, BB), 256>>>(W1, b1, W2, b2, W3, b3, lng, lnb, W4, b4);
    gather_kernel<<<dim3((NN * 32) / 256, BB), 256>>>(labels, (float4*)d_out);
}